// round 5
// baseline (speedup 1.0000x reference)
#include <cuda_runtime.h>
#include <math.h>

#define NN 256
#define DD 64
#define BB 2048
#define RANK_K 52428          // int(0.8 * 256 * 256)
#define NCHUNK 32             // node chunks; 8 nodes per chunk

typedef unsigned long long ull;

// ---------------- scratch (device globals; no allocation allowed) ------------
__device__ float g_thr;
__device__ float g_adj[NN * NN];
__device__ float g_eff[NN * DD * DD];                  // 4 MB
__device__ float g_parts[(size_t)NCHUNK * BB * DD];    // 16.8 MB

// ---------------- packed f32x2 helpers ---------------------------------------
__device__ __forceinline__ ull pk_dup(float a) {
    ull r; asm("mov.b64 %0, {%1, %1};" : "=l"(r) : "f"(a)); return r;
}
__device__ __forceinline__ void fma2(ull& d, ull a, ull b) {
    asm("fma.rn.f32x2 %0, %1, %2, %0;" : "+l"(d) : "l"(a), "l"(b));
}
__device__ __forceinline__ float2 unpk(ull v) {
    float lo, hi; asm("mov.b64 {%0, %1}, %2;" : "=f"(lo), "=f"(hi) : "l"(v));
    return make_float2(lo, hi);
}

// ---------------- misc helpers ------------------------------------------------
__device__ __forceinline__ unsigned f2ord(float f) {
    unsigned u = __float_as_uint(f);
    return (u & 0x80000000u) ? ~u : (u | 0x80000000u);
}
__device__ __forceinline__ float ord2f(unsigned u) {
    u = (u & 0x80000000u) ? (u ^ 0x80000000u) : ~u;
    return __uint_as_float(u);
}
__device__ __forceinline__ float sigmoidf_(float v) {
    return 1.0f / (1.0f + expf(-v));
}

// ---------------- kernel 1: radix-select threshold ---------------------------
__global__ void kthresh(const float* __restrict__ adj_param) {
    __shared__ unsigned hist[256];
    __shared__ unsigned s_sel;
    __shared__ int s_rank;
    unsigned prefix = 0;
    int rank = RANK_K;
    const int T = NN * NN;
    for (int pass = 3; pass >= 0; --pass) {
        for (int i = threadIdx.x; i < 256; i += blockDim.x) hist[i] = 0;
        __syncthreads();
        for (int i = threadIdx.x; i < T; i += blockDim.x) {
            unsigned u = f2ord(adj_param[i]);
            unsigned hi = (pass == 3) ? 0u : (u >> ((pass + 1) * 8));
            if (hi == prefix) atomicAdd(&hist[(u >> (pass * 8)) & 0xFF], 1u);
        }
        __syncthreads();
        if (threadIdx.x == 0) {
            unsigned cum = 0, b = 0;
            for (b = 0; b < 256; b++) {
                if (cum + hist[b] > (unsigned)rank) break;
                cum += hist[b];
            }
            s_sel = b;
            s_rank = rank - (int)cum;
        }
        __syncthreads();
        prefix = (prefix << 8) | s_sel;
        rank = s_rank;
        __syncthreads();
    }
    if (threadIdx.x == 0) g_thr = sigmoidf_(ord2f(prefix));
}

// ---------------- kernel 2: adjacency build + output -------------------------
__global__ void kadj(const float* __restrict__ adj_param, float* __restrict__ out_adj) {
    int idx = blockIdx.x * blockDim.x + threadIdx.x;
    int i = idx >> 8, j = idx & 255;
    float s = sigmoidf_(adj_param[idx]);
    float a = (s > g_thr && i != j) ? s : 0.0f;
    g_adj[idx] = a;
    if (out_adj) out_adj[idx] = a;
}

// ---------------- kernel 3: effW1 = 0.5*(I + adj^T) @ G ----------------------
__global__ void keff(const float* __restrict__ gpW1) {
    __shared__ float adjs[32][36];
    __shared__ float Gs[32][132];
    int tx = threadIdx.x & 31;
    int ty = threadIdx.x >> 5;
    int de0 = blockIdx.x * 128;
    int j0 = blockIdx.y * 32;
    float acc[4][4] = {};
    for (int i0 = 0; i0 < NN; i0 += 32) {
        for (int l = threadIdx.x; l < 32 * 32; l += 256) {
            int ii = l >> 5, jj = l & 31;
            adjs[ii][jj] = g_adj[(i0 + ii) * NN + j0 + jj];
        }
        for (int l = threadIdx.x; l < 32 * 32; l += 256) {
            int ii = l >> 5, dq = (l & 31) * 4;
            float4 v = *reinterpret_cast<const float4*>(&gpW1[(size_t)(i0 + ii) * 4096 + de0 + dq]);
            *reinterpret_cast<float4*>(&Gs[ii][dq]) = v;
        }
        __syncthreads();
#pragma unroll
        for (int k = 0; k < 32; k++) {
            float4 a4 = *reinterpret_cast<const float4*>(&adjs[k][ty * 4]);
            float4 g4 = *reinterpret_cast<const float4*>(&Gs[k][tx * 4]);
            float av[4] = {a4.x, a4.y, a4.z, a4.w};
            float gv[4] = {g4.x, g4.y, g4.z, g4.w};
#pragma unroll
            for (int jj = 0; jj < 4; jj++)
#pragma unroll
                for (int dq = 0; dq < 4; dq++) acc[jj][dq] += av[jj] * gv[dq];
        }
        __syncthreads();
    }
#pragma unroll
    for (int jj = 0; jj < 4; jj++) {
        int j = j0 + ty * 4 + jj;
        int de = de0 + tx * 4;
        float4 gd = *reinterpret_cast<const float4*>(&gpW1[(size_t)j * 4096 + de]);
        float4 o;
        o.x = 0.5f * (gd.x + acc[jj][0]);
        o.y = 0.5f * (gd.y + acc[jj][1]);
        o.z = 0.5f * (gd.z + acc[jj][2]);
        o.w = 0.5f * (gd.w + acc[jj][3]);
        *reinterpret_cast<float4*>(&g_eff[(size_t)j * 4096 + de]) = o;
    }
}

// ---------------- FFMA2 inner GEMM: acc += Xs[128x64] @ Ws[64x64] ------------
// 128 threads. tx = tid&7 (cols {4tx..4tx+3} and {32+4tx..32+4tx+3}),
// ty = tid>>3 (rows 8ty..8ty+7).
// Xs swizzled: x[r][c] at Xs[r*64 + (c ^ (((r>>3)&3)<<2))].
__device__ __forceinline__ void mm_128x64(const float* __restrict__ Xs,
                                          const float* __restrict__ Ws,
                                          int tx, int ty, unsigned xsw,
                                          ull acc[8][4]) {
#pragma unroll 2
    for (int kq = 0; kq < 16; kq++) {
        float4 xq[8];
#pragma unroll
        for (int i = 0; i < 8; i++)
            xq[i] = *reinterpret_cast<const float4*>(&Xs[(8 * ty + i) * 64 + ((4 * kq) ^ xsw)]);
#pragma unroll
        for (int dk = 0; dk < 4; dk++) {
            int k = 4 * kq + dk;
            ulonglong2 wA = *reinterpret_cast<const ulonglong2*>(&Ws[k * 64 + 4 * tx]);
            ulonglong2 wB = *reinterpret_cast<const ulonglong2*>(&Ws[k * 64 + 32 + 4 * tx]);
#pragma unroll
            for (int i = 0; i < 8; i++) {
                float a = (dk == 0) ? xq[i].x : (dk == 1) ? xq[i].y : (dk == 2) ? xq[i].z : xq[i].w;
                ull a2 = pk_dup(a);
                fma2(acc[i][0], a2, wA.x);
                fma2(acc[i][1], a2, wA.y);
                fma2(acc[i][2], a2, wB.x);
                fma2(acc[i][3], a2, wB.y);
            }
        }
    }
}

// ---------------- fused kernel: per-node MLP + on-the-fly eff-GEMM -----------
// Block (bx, by): batch rows [bx*128, bx*128+128), nodes [by*8, by*8+8).
// For each node: node_tile = relu(x@W1+b1)@W2+b2 (via smem), then
// acc_g += node_tile @ eff[n].  acc_g written to g_parts[by].
__global__ void __launch_bounds__(128, 2) kfused(
    const float* __restrict__ x, const float* __restrict__ W1,
    const float* __restrict__ b1, const float* __restrict__ W2,
    const float* __restrict__ b2) {
    __shared__ __align__(16) float Xs[128 * 64];
    __shared__ __align__(16) float Ws[64 * 64];
    int b0 = blockIdx.x * 128;
    int n0 = blockIdx.y * (NN / NCHUNK);
    int tid = threadIdx.x;
    int tx = tid & 7, ty = tid >> 3;
    unsigned xsw = (unsigned)((ty & 3) << 2);

    ull acc_g[8][4] = {};

    for (int nn = 0; nn < NN / NCHUNK; nn++) {
        int n = n0 + nn;
        // ---- load x tile (swizzled) + W1 ----
#pragma unroll
        for (int m = 0; m < 16; m++) {
            int l = tid + m * 128;
            int r = l >> 4, cq = (l & 15) * 4;
            float4 v = *reinterpret_cast<const float4*>(&x[(size_t)(b0 + r) * (NN * DD) + n * DD + cq]);
            *reinterpret_cast<float4*>(&Xs[r * 64 + (cq ^ (((r >> 3) & 3) << 2))]) = v;
        }
#pragma unroll
        for (int m = 0; m < 8; m++) {
            int l = tid + m * 128;
            int k = l >> 4, cq = (l & 15) * 4;
            *reinterpret_cast<float4*>(&Ws[k * 64 + cq]) =
                *reinterpret_cast<const float4*>(&W1[(size_t)n * 4096 + k * 64 + cq]);
        }
        __syncthreads();

        // ---- layer 1 ----
        ull acc[8][4] = {};
        mm_128x64(Xs, Ws, tx, ty, xsw, acc);
        __syncthreads();

        // h = relu(acc + b1) -> Xs; Ws <- W2
        {
            float4 bA = *reinterpret_cast<const float4*>(&b1[n * DD + 4 * tx]);
            float4 bB = *reinterpret_cast<const float4*>(&b1[n * DD + 32 + 4 * tx]);
#pragma unroll
            for (int i = 0; i < 8; i++) {
                int r = 8 * ty + i;
                float2 p0 = unpk(acc[i][0]);
                float2 p1 = unpk(acc[i][1]);
                float2 p2 = unpk(acc[i][2]);
                float2 p3 = unpk(acc[i][3]);
                float4 hA = {fmaxf(p0.x + bA.x, 0.0f), fmaxf(p0.y + bA.y, 0.0f),
                             fmaxf(p1.x + bA.z, 0.0f), fmaxf(p1.y + bA.w, 0.0f)};
                float4 hB = {fmaxf(p2.x + bB.x, 0.0f), fmaxf(p2.y + bB.y, 0.0f),
                             fmaxf(p3.x + bB.z, 0.0f), fmaxf(p3.y + bB.w, 0.0f)};
                *reinterpret_cast<float4*>(&Xs[r * 64 + ((4 * tx) ^ xsw)]) = hA;
                *reinterpret_cast<float4*>(&Xs[r * 64 + ((32 + 4 * tx) ^ xsw)]) = hB;
            }
        }
#pragma unroll
        for (int m = 0; m < 8; m++) {
            int l = tid + m * 128;
            int k = l >> 4, cq = (l & 15) * 4;
            *reinterpret_cast<float4*>(&Ws[k * 64 + cq]) =
                *reinterpret_cast<const float4*>(&W2[(size_t)n * 4096 + k * 64 + cq]);
        }
        __syncthreads();

        // ---- layer 2 ----
        ull acc2[8][4] = {};
        mm_128x64(Xs, Ws, tx, ty, xsw, acc2);
        __syncthreads();

        // node = acc2 + b2 -> Xs; Ws <- eff[n]
        {
            float4 cA = *reinterpret_cast<const float4*>(&b2[n * DD + 4 * tx]);
            float4 cB = *reinterpret_cast<const float4*>(&b2[n * DD + 32 + 4 * tx]);
#pragma unroll
            for (int i = 0; i < 8; i++) {
                int r = 8 * ty + i;
                float2 p0 = unpk(acc2[i][0]);
                float2 p1 = unpk(acc2[i][1]);
                float2 p2 = unpk(acc2[i][2]);
                float2 p3 = unpk(acc2[i][3]);
                float4 oA = {p0.x + cA.x, p0.y + cA.y, p1.x + cA.z, p1.y + cA.w};
                float4 oB = {p2.x + cB.x, p2.y + cB.y, p3.x + cB.z, p3.y + cB.w};
                *reinterpret_cast<float4*>(&Xs[r * 64 + ((4 * tx) ^ xsw)]) = oA;
                *reinterpret_cast<float4*>(&Xs[r * 64 + ((32 + 4 * tx) ^ xsw)]) = oB;
            }
        }
#pragma unroll
        for (int m = 0; m < 8; m++) {
            int l = tid + m * 128;
            int k = l >> 4, cq = (l & 15) * 4;
            *reinterpret_cast<float4*>(&Ws[k * 64 + cq]) =
                *reinterpret_cast<const float4*>(&g_eff[(size_t)n * 4096 + k * 64 + cq]);
        }
        __syncthreads();

        // ---- GEMM3: acc_g += node @ eff[n] ----
        mm_128x64(Xs, Ws, tx, ty, xsw, acc_g);
        __syncthreads();
    }

    // write partials
#pragma unroll
    for (int i = 0; i < 8; i++) {
        int r = b0 + 8 * ty + i;
        float2 p0 = unpk(acc_g[i][0]);
        float2 p1 = unpk(acc_g[i][1]);
        float2 p2 = unpk(acc_g[i][2]);
        float2 p3 = unpk(acc_g[i][3]);
        float4 oA = {p0.x, p0.y, p1.x, p1.y};
        float4 oB = {p2.x, p2.y, p3.x, p3.y};
        size_t base = ((size_t)blockIdx.y * BB + r) * 64;
        *reinterpret_cast<float4*>(&g_parts[base + 4 * tx]) = oA;
        *reinterpret_cast<float4*>(&g_parts[base + 32 + 4 * tx]) = oB;
    }
}

// ---------------- kernel: reduce partials + relu + gpW2 epilogue -------------
__global__ void kfinal(const float* __restrict__ gpb1, const float* __restrict__ gpW2,
                       const float* __restrict__ gpb2, float* __restrict__ out) {
    __shared__ float gs[64][65];
    __shared__ float w2s[64][33];
    __shared__ float b2s[32];
    int b0 = blockIdx.x * 64;
    for (int l = threadIdx.x; l < 4096; l += 256) {
        int r = l >> 6, d = l & 63;
        float s = gpb1[d];
#pragma unroll
        for (int ks = 0; ks < NCHUNK; ks++) s += g_parts[((size_t)ks * BB + b0 + r) * 64 + d];
        gs[r][d] = fmaxf(s, 0.0f);
    }
    for (int l = threadIdx.x; l < 2048; l += 256) {
        int d = l >> 5, h = l & 31;
        w2s[d][h] = gpW2[l];
    }
    if (threadIdx.x < 32) b2s[threadIdx.x] = gpb2[threadIdx.x];
    __syncthreads();
    int h = threadIdx.x & 31, rg = threadIdx.x >> 5;
#pragma unroll
    for (int i = 0; i < 8; i++) {
        int r = rg * 8 + i;
        float s = b2s[h];
#pragma unroll 16
        for (int d = 0; d < 64; d++) s += gs[r][d] * w2s[d][h];
        out[(size_t)(b0 + r) * 32 + h] = s;
    }
}

// ---------------- launch ------------------------------------------------------
extern "C" void kernel_launch(void* const* d_in, const int* in_sizes, int n_in,
                              void* d_out, int out_size) {
    const float* x         = (const float*)d_in[0];
    const float* adj_param = (const float*)d_in[1];
    const float* W1        = (const float*)d_in[2];
    const float* b1        = (const float*)d_in[3];
    const float* W2        = (const float*)d_in[4];
    const float* b2        = (const float*)d_in[5];
    const float* gpW1      = (const float*)d_in[6];
    const float* gpb1      = (const float*)d_in[7];
    const float* gpW2      = (const float*)d_in[8];
    const float* gpb2      = (const float*)d_in[9];
    float* out = (float*)d_out;
    float* adj_out = (out_size >= 131072) ? (out + BB * 32) : nullptr;

    kthresh<<<1, 1024>>>(adj_param);
    kadj<<<64, 1024>>>(adj_param, adj_out);
    keff<<<dim3(32, 8), 256>>>(gpW1);
    kfused<<<dim3(BB / 128, NCHUNK), 128>>>(x, W1, b1, W2, b2);
    kfinal<<<BB / 64, 256>>>(gpb1, gpW2, gpb2, out);
}

// round 7
// speedup vs baseline: 1.4838x; 1.4838x over previous
#include <cuda_runtime.h>
#include <math.h>
#include <cstdint>

#define NN 256
#define DD 64
#define BB 2048
#define RANK_K 52428          // int(0.8 * 256 * 256)
#define NCHUNK 32             // node chunks; 8 nodes per chunk

// ---------------- scratch (device globals; no allocation allowed) ------------
__device__ float g_thr;
__device__ float g_adj[NN * NN];
__device__ float g_eff[NN * DD * DD];                  // 4 MB
__device__ float g_parts[(size_t)NCHUNK * BB * DD];    // 16.8 MB

// ---------------- smem map for mma kernel (dynamic) --------------------------
#define SM_XHI  0                        // 128x64 bf16, SW128-swizzled rows of 128B
#define SM_XLO  16384
#define SM_WHI  32768                    // 64x64 bf16 [k][n] row-major swizzled
#define SM_WLO  40960
#define SM_BIAS 49152                    // 128 floats: bias1[64], bias2[64]
#define SM_TOT  49664

// ---------------- helpers -----------------------------------------------------
__device__ __forceinline__ uint32_t smem_u32(const void* p) {
    uint32_t a;
    asm("{ .reg .u64 t; cvta.to.shared.u64 t, %1; cvt.u32.u64 %0, t; }" : "=r"(a) : "l"(p));
    return a;
}
__device__ __forceinline__ uint32_t sw128(uint32_t o) { return o ^ ((o >> 3) & 0x70u); }

__device__ __forceinline__ void ldm_x4(uint32_t r[4], uint32_t addr) {
    asm volatile("ldmatrix.sync.aligned.m8n8.x4.shared.b16 {%0,%1,%2,%3}, [%4];"
                 : "=r"(r[0]), "=r"(r[1]), "=r"(r[2]), "=r"(r[3]) : "r"(addr));
}
__device__ __forceinline__ void ldm_x4_t(uint32_t r[4], uint32_t addr) {
    asm volatile("ldmatrix.sync.aligned.m8n8.x4.trans.shared.b16 {%0,%1,%2,%3}, [%4];"
                 : "=r"(r[0]), "=r"(r[1]), "=r"(r[2]), "=r"(r[3]) : "r"(addr));
}
__device__ __forceinline__ void mma16816(float c[4], const uint32_t a[4], const uint32_t b[2]) {
    asm volatile(
        "mma.sync.aligned.m16n8k16.row.col.f32.bf16.bf16.f32 "
        "{%0,%1,%2,%3}, {%4,%5,%6,%7}, {%8,%9}, {%0,%1,%2,%3};"
        : "+f"(c[0]), "+f"(c[1]), "+f"(c[2]), "+f"(c[3])
        : "r"(a[0]), "r"(a[1]), "r"(a[2]), "r"(a[3]), "r"(b[0]), "r"(b[1]));
}
// pack (x0,x1) -> bf16 hi pair + bf16 lo-residual pair (memory order: x0 in low half)
__device__ __forceinline__ void split2(float x0, float x1, uint32_t& hi, uint32_t& lo) {
    uint32_t h;
    asm("cvt.rn.bf16x2.f32 %0, %1, %2;" : "=r"(h) : "f"(x1), "f"(x0));
    float h0 = __uint_as_float(h << 16);
    float h1 = __uint_as_float(h & 0xffff0000u);
    float l0 = x0 - h0, l1 = x1 - h1;
    asm("cvt.rn.bf16x2.f32 %0, %1, %2;" : "=r"(lo) : "f"(l1), "f"(l0));
    hi = h;
}
// ldmatrix address for the 4-tile layout used by both A and B(trans)
__device__ __forceinline__ uint32_t ldm_addr(uint32_t base, int row0, int colbyte0, int lane) {
    int grp = lane >> 3, lr = lane & 7;
    uint32_t off = (uint32_t)((row0 + lr + (grp & 1) * 8) * 128 + colbyte0 + (grp >> 1) * 16);
    return base + sw128(off);
}

__device__ __forceinline__ unsigned f2ord(float f) {
    unsigned u = __float_as_uint(f);
    return (u & 0x80000000u) ? ~u : (u | 0x80000000u);
}
__device__ __forceinline__ float ord2f(unsigned u) {
    u = (u & 0x80000000u) ? (u ^ 0x80000000u) : ~u;
    return __uint_as_float(u);
}
__device__ __forceinline__ float sigmoidf_(float v) {
    return 1.0f / (1.0f + expf(-v));
}

// ---------------- kernel 1: radix-select threshold ---------------------------
__global__ void kthresh(const float* __restrict__ adj_param) {
    __shared__ unsigned hist[256];
    __shared__ unsigned s_sel;
    __shared__ int s_rank;
    unsigned prefix = 0;
    int rank = RANK_K;
    const int T = NN * NN;
    for (int pass = 3; pass >= 0; --pass) {
        for (int i = threadIdx.x; i < 256; i += blockDim.x) hist[i] = 0;
        __syncthreads();
        for (int i = threadIdx.x; i < T; i += blockDim.x) {
            unsigned u = f2ord(adj_param[i]);
            unsigned hi = (pass == 3) ? 0u : (u >> ((pass + 1) * 8));
            if (hi == prefix) atomicAdd(&hist[(u >> (pass * 8)) & 0xFF], 1u);
        }
        __syncthreads();
        if (threadIdx.x == 0) {
            unsigned cum = 0, b = 0;
            for (b = 0; b < 256; b++) {
                if (cum + hist[b] > (unsigned)rank) break;
                cum += hist[b];
            }
            s_sel = b;
            s_rank = rank - (int)cum;
        }
        __syncthreads();
        prefix = (prefix << 8) | s_sel;
        rank = s_rank;
        __syncthreads();
    }
    if (threadIdx.x == 0) g_thr = sigmoidf_(ord2f(prefix));
}

// ---------------- kernel 2: adjacency build + output -------------------------
__global__ void kadj(const float* __restrict__ adj_param, float* __restrict__ out_adj) {
    int idx = blockIdx.x * blockDim.x + threadIdx.x;
    int i = idx >> 8, j = idx & 255;
    float s = sigmoidf_(adj_param[idx]);
    float a = (s > g_thr && i != j) ? s : 0.0f;
    g_adj[idx] = a;
    if (out_adj) out_adj[idx] = a;
}

// ---------------- kernel 3: effW1 = 0.5*(I + adj^T) @ G ----------------------
__global__ void keff(const float* __restrict__ gpW1) {
    __shared__ float adjs[32][36];
    __shared__ float Gs[32][132];
    int tx = threadIdx.x & 31;
    int ty = threadIdx.x >> 5;
    int de0 = blockIdx.x * 128;
    int j0 = blockIdx.y * 32;
    float acc[4][4] = {};
    for (int i0 = 0; i0 < NN; i0 += 32) {
        for (int l = threadIdx.x; l < 32 * 32; l += 256) {
            int ii = l >> 5, jj = l & 31;
            adjs[ii][jj] = g_adj[(i0 + ii) * NN + j0 + jj];
        }
        for (int l = threadIdx.x; l < 32 * 32; l += 256) {
            int ii = l >> 5, dq = (l & 31) * 4;
            float4 v = *reinterpret_cast<const float4*>(&gpW1[(size_t)(i0 + ii) * 4096 + de0 + dq]);
            *reinterpret_cast<float4*>(&Gs[ii][dq]) = v;
        }
        __syncthreads();
#pragma unroll
        for (int k = 0; k < 32; k++) {
            float4 a4 = *reinterpret_cast<const float4*>(&adjs[k][ty * 4]);
            float4 g4 = *reinterpret_cast<const float4*>(&Gs[k][tx * 4]);
            float av[4] = {a4.x, a4.y, a4.z, a4.w};
            float gv[4] = {g4.x, g4.y, g4.z, g4.w};
#pragma unroll
            for (int jj = 0; jj < 4; jj++)
#pragma unroll
                for (int dq = 0; dq < 4; dq++) acc[jj][dq] += av[jj] * gv[dq];
        }
        __syncthreads();
    }
#pragma unroll
    for (int jj = 0; jj < 4; jj++) {
        int j = j0 + ty * 4 + jj;
        int de = de0 + tx * 4;
        float4 gd = *reinterpret_cast<const float4*>(&gpW1[(size_t)j * 4096 + de]);
        float4 o;
        o.x = 0.5f * (gd.x + acc[jj][0]);
        o.y = 0.5f * (gd.y + acc[jj][1]);
        o.z = 0.5f * (gd.z + acc[jj][2]);
        o.w = 0.5f * (gd.w + acc[jj][3]);
        *reinterpret_cast<float4*>(&g_eff[(size_t)j * 4096 + de]) = o;
    }
}

// ---------------- bf16x3 GEMM: acc += X[128x64] @ W[64x64] -------------------
// warp w handles rows 32w..32w+31 (two m16 tiles), all 64 cols (8 n8 tiles).
__device__ __forceinline__ void wgemm(uint32_t sb, int w, int lane, float acc[2][8][4]) {
#pragma unroll
    for (int pass = 0; pass < 3; pass++) {
        uint32_t ab = sb + (pass == 2 ? SM_XLO : SM_XHI);
        uint32_t bb = sb + (pass == 1 ? SM_WLO : SM_WHI);
#pragma unroll
        for (int ks = 0; ks < 4; ks++) {
            uint32_t a[2][4];
#pragma unroll
            for (int mt = 0; mt < 2; mt++)
                ldm_x4(a[mt], ldm_addr(ab, 32 * w + 16 * mt, 32 * ks, lane));
            uint32_t b[8][2];
#pragma unroll
            for (int p = 0; p < 4; p++) {
                uint32_t r[4];
                ldm_x4_t(r, ldm_addr(bb, 16 * ks, 32 * p, lane));
                b[2 * p][0] = r[0]; b[2 * p][1] = r[1];
                b[2 * p + 1][0] = r[2]; b[2 * p + 1][1] = r[3];
            }
#pragma unroll
            for (int mt = 0; mt < 2; mt++)
#pragma unroll
                for (int nt = 0; nt < 8; nt++)
                    mma16816(acc[mt][nt], a[mt], b[nt]);
        }
    }
}

// fill W tile (64x64 f32 row-major) into WHI/WLO (swizzled bf16)
__device__ __forceinline__ void fillW(char* smem, const float* __restrict__ Wp, int tid) {
#pragma unroll
    for (int it = 0; it < 16; it++) {
        int l = tid + it * 128;          // pair index
        int k = l >> 5, cp = l & 31;
        float2 v = *reinterpret_cast<const float2*>(&Wp[k * 64 + 2 * cp]);
        uint32_t hi, lo;
        split2(v.x, v.y, hi, lo);
        uint32_t off = sw128((uint32_t)(k * 128 + cp * 4));
        *reinterpret_cast<uint32_t*>(smem + SM_WHI + off) = hi;
        *reinterpret_cast<uint32_t*>(smem + SM_WLO + off) = lo;
    }
}

// epilogue: X <- (acc + bias) [relu], split into XHI/XLO (warp-private rows)
__device__ __forceinline__ void epilogue(char* smem, const float acc[2][8][4],
                                         const float* __restrict__ bias, bool relu,
                                         int w, int g, int tq) {
#pragma unroll
    for (int mt = 0; mt < 2; mt++) {
#pragma unroll
        for (int nt = 0; nt < 8; nt++) {
            int col = 8 * nt + 2 * tq;
            float2 bv = *reinterpret_cast<const float2*>(&bias[col]);
            float x0 = acc[mt][nt][0] + bv.x, x1 = acc[mt][nt][1] + bv.y;
            float x2 = acc[mt][nt][2] + bv.x, x3 = acc[mt][nt][3] + bv.y;
            if (relu) {
                x0 = fmaxf(x0, 0.0f); x1 = fmaxf(x1, 0.0f);
                x2 = fmaxf(x2, 0.0f); x3 = fmaxf(x3, 0.0f);
            }
            int row = 32 * w + 16 * mt + g;
            uint32_t hi, lo;
            split2(x0, x1, hi, lo);
            uint32_t off = sw128((uint32_t)(row * 128 + col * 2));
            *reinterpret_cast<uint32_t*>(smem + SM_XHI + off) = hi;
            *reinterpret_cast<uint32_t*>(smem + SM_XLO + off) = lo;
            split2(x2, x3, hi, lo);
            off = sw128((uint32_t)((row + 8) * 128 + col * 2));
            *reinterpret_cast<uint32_t*>(smem + SM_XHI + off) = hi;
            *reinterpret_cast<uint32_t*>(smem + SM_XLO + off) = lo;
        }
    }
}

// ---------------- fused tensor-core kernel (legacy mma.sync) -----------------
// Block (bx, by): rows [bx*128,+128), nodes [by*8,+8). 128 threads, 4 warps.
__global__ void __launch_bounds__(128) kfused_mma(
    const float* __restrict__ x, const float* __restrict__ W1,
    const float* __restrict__ b1, const float* __restrict__ W2,
    const float* __restrict__ b2) {
    extern __shared__ char smem[];
    uint32_t sb = smem_u32(smem);
    float* bias = reinterpret_cast<float*>(smem + SM_BIAS);   // [0:64)=b1, [64:128)=b2
    int tid = threadIdx.x, w = tid >> 5, lane = tid & 31;
    int g = lane >> 2, tq = lane & 3;
    int b0 = blockIdx.x * 128;
    int n0 = blockIdx.y * 8;

    float acc_g[2][8][4] = {};

    for (int nn = 0; nn < 8; nn++) {
        int n = n0 + nn;
        // ---- fill X (split+swizzle), W1, biases ----
#pragma unroll
        for (int it = 0; it < 32; it++) {
            int l = tid + it * 128;      // pair index 0..4095
            int r = l >> 5, cp = l & 31;
            float2 v = *reinterpret_cast<const float2*>(
                &x[(size_t)(b0 + r) * (NN * DD) + n * DD + 2 * cp]);
            uint32_t hi, lo;
            split2(v.x, v.y, hi, lo);
            uint32_t off = sw128((uint32_t)(r * 128 + cp * 4));
            *reinterpret_cast<uint32_t*>(smem + SM_XHI + off) = hi;
            *reinterpret_cast<uint32_t*>(smem + SM_XLO + off) = lo;
        }
        fillW(smem, W1 + (size_t)n * 4096, tid);
        if (tid < 64) bias[tid] = b1[n * DD + tid];
        else bias[tid] = b2[n * DD + tid - 64];
        __syncthreads();

        // ---- layer 1 ----
        {
            float acc[2][8][4] = {};
            wgemm(sb, w, lane, acc);
            __syncthreads();
            epilogue(smem, acc, bias, true, w, g, tq);     // h = relu(.+b1)
        }
        fillW(smem, W2 + (size_t)n * 4096, tid);
        __syncthreads();

        // ---- layer 2 ----
        {
            float acc[2][8][4] = {};
            wgemm(sb, w, lane, acc);
            __syncthreads();
            epilogue(smem, acc, bias + 64, false, w, g, tq);  // node = .+b2
        }
        fillW(smem, g_eff + (size_t)n * 4096, tid);
        __syncthreads();

        // ---- GEMM3: acc_g += node @ eff[n] ----
        wgemm(sb, w, lane, acc_g);
        __syncthreads();
    }

    // ---- write partials ----
#pragma unroll
    for (int mt = 0; mt < 2; mt++) {
#pragma unroll
        for (int nt = 0; nt < 8; nt++) {
            int row = b0 + 32 * w + 16 * mt + g;
            int col = 8 * nt + 2 * tq;
            size_t base = ((size_t)blockIdx.y * BB + row) * 64 + col;
            float2 o0 = {acc_g[mt][nt][0], acc_g[mt][nt][1]};
            float2 o1 = {acc_g[mt][nt][2], acc_g[mt][nt][3]};
            *reinterpret_cast<float2*>(&g_parts[base]) = o0;
            *reinterpret_cast<float2*>(&g_parts[base + 8 * 64]) = o1;
        }
    }
}

// ---------------- kernel: reduce partials + relu + gpW2 epilogue -------------
__global__ void kfinal(const float* __restrict__ gpb1, const float* __restrict__ gpW2,
                       const float* __restrict__ gpb2, float* __restrict__ out) {
    __shared__ float gs[64][65];
    __shared__ float w2s[64][33];
    __shared__ float b2s[32];
    int b0 = blockIdx.x * 64;
    for (int l = threadIdx.x; l < 4096; l += 256) {
        int r = l >> 6, d = l & 63;
        float s = gpb1[d];
#pragma unroll
        for (int ks = 0; ks < NCHUNK; ks++) s += g_parts[((size_t)ks * BB + b0 + r) * 64 + d];
        gs[r][d] = fmaxf(s, 0.0f);
    }
    for (int l = threadIdx.x; l < 2048; l += 256) {
        int d = l >> 5, h = l & 31;
        w2s[d][h] = gpW2[l];
    }
    if (threadIdx.x < 32) b2s[threadIdx.x] = gpb2[threadIdx.x];
    __syncthreads();
    int h = threadIdx.x & 31, rg = threadIdx.x >> 5;
#pragma unroll
    for (int i = 0; i < 8; i++) {
        int r = rg * 8 + i;
        float s = b2s[h];
#pragma unroll 16
        for (int d = 0; d < 64; d++) s += gs[r][d] * w2s[d][h];
        out[(size_t)(b0 + r) * 32 + h] = s;
    }
}

// ---------------- launch ------------------------------------------------------
extern "C" void kernel_launch(void* const* d_in, const int* in_sizes, int n_in,
                              void* d_out, int out_size) {
    const float* x         = (const float*)d_in[0];
    const float* adj_param = (const float*)d_in[1];
    const float* W1        = (const float*)d_in[2];
    const float* b1        = (const float*)d_in[3];
    const float* W2        = (const float*)d_in[4];
    const float* b2        = (const float*)d_in[5];
    const float* gpW1      = (const float*)d_in[6];
    const float* gpb1      = (const float*)d_in[7];
    const float* gpW2      = (const float*)d_in[8];
    const float* gpb2      = (const float*)d_in[9];
    float* out = (float*)d_out;
    float* adj_out = (out_size >= 131072) ? (out + BB * 32) : nullptr;

    cudaFuncSetAttribute(kfused_mma, cudaFuncAttributeMaxDynamicSharedMemorySize, SM_TOT);

    kthresh<<<1, 1024>>>(adj_param);
    kadj<<<64, 1024>>>(adj_param, adj_out);
    keff<<<dim3(32, 8), 256>>>(gpW1);
    kfused_mma<<<dim3(BB / 128, NCHUNK), 128, SM_TOT>>>(x, W1, b1, W2, b2);
    kfinal<<<BB / 64, 256>>>(gpb1, gpW2, gpb2, out);
}